// round 10
// baseline (speedup 1.0000x reference)
#include <cuda_runtime.h>
#include <cstring>

#define NLAYERS 200
#define KSIZE   7
#define L_IN    1388
#define FC_IN   188
#define FC_OUT  91
#define NT      128        // 4 warps = 2 rows x 2 warps
#define TSTEP   16         // layers per super-step (overlap = 6*16 = 96 elements)
#define STGN    1392       // per-row float stage

// Packed dual-fp32 FMA (Blackwell f32x2).
static __device__ __forceinline__ float2 ffma2(float2 a, float2 b, float2 c) {
    unsigned long long ua, ub, uc, ud;
    memcpy(&ua, &a, 8); memcpy(&ub, &b, 8); memcpy(&uc, &c, 8);
    asm("fma.rn.f32x2 %0, %1, %2, %3;" : "=l"(ud) : "l"(ua), "l"(ub), "l"(uc));
    float2 d; memcpy(&d, &ud, 8);
    return d;
}

// Far-pair conv phase: lane l owns packed positions g = l*C+c of this warp's
// window, P[g] = (h[g], h[g+D]), D = 32*C. All taps pair-aligned; halo via
// rotated SHFL (lane-31 seam takes lane0's .y). REQUIRES C >= 6: the 6-element
// look-ahead must fit within the next lane's chunk.
template<int C>
static __device__ __forceinline__ void phase(float2* p, int layer0, int nl,
                                             const float2* __restrict__ ws2,
                                             const float2* __restrict__ bs2,
                                             int lane)
{
    static_assert(C >= 6, "seam halo spans one lane only");
    #pragma unroll 1
    for (int i = 0; i < nl; i++) {
        const int L = layer0 + i;
        float2 w[KSIZE];
        #pragma unroll
        for (int k = 0; k < KSIZE; k++) w[k] = ws2[L * KSIZE + k];
        const float2 b = bs2[L];

        float2 rot[6];
        #pragma unroll
        for (int m = 0; m < 6; m++) {
            float rx = __shfl_sync(0xffffffffu, p[m].x, lane + 1); // 31 wraps to 0
            float ry = __shfl_sync(0xffffffffu, p[m].y, lane + 1);
            rot[m] = make_float2((lane == 31) ? ry : rx, ry);
        }

        const bool relu = (L != NLAYERS - 1);
        #pragma unroll
        for (int j = 0; j < C; j++) {
            float2 acc = b;
            acc = ffma2(w[0], p[j], acc);
            #pragma unroll
            for (int k = 1; k < KSIZE; k++) {
                float2 v = (j + k < C) ? p[j + k] : rot[j + k - C];
                acc = ffma2(w[k], v, acc);
            }
            if (relu) { acc.x = fmaxf(acc.x, 0.0f); acc.y = fmaxf(acc.y, 0.0f); }
            p[j] = acc;
        }
    }
}

// Super-step exchange. VOLD = valid length at the step START (valid now is
// VN = VOLD - 96). Warp A (half 0) owned [0, 2*DO); warp B owned
// [VOLD-2*DO, VOLD). A publishes [0, VOLD-2*DO), B publishes up to VN; both
// re-pack new windows at chunk CN (B anchored at VN). DUP: both read [0,2*DN).
template<int CO, int CN, int VOLD, bool DUP>
static __device__ __forceinline__ void exchange(float2* p, float* stg,
                                                int lane, int half, int barid)
{
    const int DO = 32 * CO, DN = 32 * CN, VN = VOLD - 6 * TSTEP;
    if (half == 0) {
        const int limit = VOLD - 2 * DO;
        #pragma unroll
        for (int c = 0; c < CO; c++) {
            int l = lane * CO + c;
            if (l < limit)      stg[l]      = p[c].x;
            if (DO + l < limit) stg[DO + l] = p[c].y;
        }
    } else {
        const int base = VOLD - 2 * DO;
        #pragma unroll
        for (int c = 0; c < CO; c++) {
            int l = lane * CO + c;
            stg[base + l] = p[c].x;
            if (l < DO - 6 * TSTEP) stg[base + DO + l] = p[c].y;
        }
    }
    asm volatile("bar.sync %0, 64;" :: "r"(barid) : "memory");
    const int base2 = (DUP || half == 0) ? 0 : (VN - 2 * DN);
    #pragma unroll
    for (int c = 0; c < CN; c++) {
        int l = lane * CN + c;
        p[c] = make_float2(stg[base2 + l], stg[base2 + DN + l]);
    }
    asm volatile("bar.sync %0, 64;" :: "r"(barid) : "memory");
}

__global__ __launch_bounds__(NT, 4)
void conv200_kernel(const float* __restrict__ x,
                    const float* __restrict__ conv_w,
                    const float* __restrict__ conv_b,
                    const float* __restrict__ fc_w,
                    const float* __restrict__ fc_b,
                    float* __restrict__ out)
{
    __shared__ __align__(16) float stg_all[2][STGN];   // 11.1 KB
    __shared__ float2 ws2[NLAYERS * KSIZE];            // 11.2 KB packed (w,w)
    __shared__ float2 bs2[NLAYERS];                    // 1.6 KB packed (b,b)

    const int t    = threadIdx.x;
    const int wid  = t >> 5;
    const int lane = t & 31;
    const int rowc = wid >> 1;     // row within CTA
    const int half = wid & 1;      // 0 = left warp, 1 = right warp
    const int barid = 1 + rowc;

    for (int j = t; j < NLAYERS * KSIZE; j += NT) {
        float w = conv_w[j];
        ws2[j] = make_float2(w, w);
    }
    for (int j = t; j < NLAYERS; j += NT) {
        float b = conv_b[j];
        bs2[j] = make_float2(b, b);
    }

    const int row = blockIdx.x * 2 + rowc;
    const float* xr = x + (size_t)row * L_IN;
    float* stg = stg_all[rowc];

    // both warps of the row cooperatively load it (coalesced)
    for (int j = (t & 63); j < L_IN; j += 64) stg[j] = __ldg(&xr[j]);
    __syncthreads();

    // initial far-pack: C=12, D=384; A window [0,768), B window [620,1388)
    float2 p[12];
    {
        const int base = half ? (L_IN - 768) : 0;
        #pragma unroll
        for (int c = 0; c < 12; c++) {
            int l = lane * 12 + c;
            p[c] = make_float2(stg[base + l], stg[base + 384 + l]);
        }
    }
    asm volatile("bar.sync %0, 64;" :: "r"(barid) : "memory");

    // ---- 200 layers: 11 super-steps of 16 + 24-layer duplicated tail.
    // C floored at 6 (seam-halo constraint). VOLD(step k) = 1388 - 96k.
    phase<12>(p,   0, TSTEP, ws2, bs2, lane); exchange<12, 11, 1388, false>(p, stg, lane, half, barid);
    phase<11>(p,  16, TSTEP, ws2, bs2, lane); exchange<11, 11, 1292, false>(p, stg, lane, half, barid);
    phase<11>(p,  32, TSTEP, ws2, bs2, lane); exchange<11, 10, 1196, false>(p, stg, lane, half, barid);
    phase<10>(p,  48, TSTEP, ws2, bs2, lane); exchange<10,  9, 1100, false>(p, stg, lane, half, barid);
    phase< 9>(p,  64, TSTEP, ws2, bs2, lane); exchange< 9,  8, 1004, false>(p, stg, lane, half, barid);
    phase< 8>(p,  80, TSTEP, ws2, bs2, lane); exchange< 8,  8,  908, false>(p, stg, lane, half, barid);
    phase< 8>(p,  96, TSTEP, ws2, bs2, lane); exchange< 8,  7,  812, false>(p, stg, lane, half, barid);
    phase< 7>(p, 112, TSTEP, ws2, bs2, lane); exchange< 7,  6,  716, false>(p, stg, lane, half, barid);
    phase< 6>(p, 128, TSTEP, ws2, bs2, lane); exchange< 6,  6,  620, false>(p, stg, lane, half, barid);
    phase< 6>(p, 144, TSTEP, ws2, bs2, lane); exchange< 6,  6,  524, false>(p, stg, lane, half, barid);
    phase< 6>(p, 160, TSTEP, ws2, bs2, lane); exchange< 6,  6,  428, true >(p, stg, lane, half, barid);
    // duplicated tail: both warps, window [0,384), layers 176..199.
    // stg garbage at [332,384) contaminates leftward to exactly 332-144 = 188.
    phase< 6>(p, 176, 24, ws2, bs2, lane);

    // ---- gather final 188 elements (all in x half; warp A publishes) ----
    if (half == 0) {
        #pragma unroll
        for (int c = 0; c < 6; c++) stg[lane * 6 + c] = p[c].x;   // fills [0,192)
    }
    asm volatile("bar.sync %0, 64;" :: "r"(barid) : "memory");

    // ---- FC 188->91 + sigmoid, outputs split across the two warps ----
    {
        const float2* hv2 = reinterpret_cast<const float2*>(stg);
        const float2* fw2 = reinterpret_cast<const float2*>(fc_w);
        const int o0   = half ? (46 + lane) : lane;            // A: 0..31, B: 46..77
        const bool has1 = half ? (lane < 13) : (lane < 14);
        const int o1   = has1 ? (half ? (78 + lane) : (32 + lane)) : o0;
        const float2* w0 = fw2 + (size_t)o0 * (FC_IN / 2);
        const float2* w1 = fw2 + (size_t)o1 * (FC_IN / 2);
        float2 a0 = make_float2(0.0f, 0.0f), a1 = make_float2(0.0f, 0.0f);
        #pragma unroll 2
        for (int j = 0; j < FC_IN / 2; j++) {
            float2 hv = hv2[j];
            a0 = ffma2(__ldg(&w0[j]), hv, a0);
            a1 = ffma2(__ldg(&w1[j]), hv, a1);
        }
        float* orow = out + (size_t)row * FC_OUT;
        float s0 = a0.x + a0.y + __ldg(&fc_b[o0]);
        orow[o0] = 1.0f / (1.0f + __expf(-s0));
        if (has1) {
            float s1 = a1.x + a1.y + __ldg(&fc_b[o1]);
            orow[o1] = 1.0f / (1.0f + __expf(-s1));
        }
    }
}

extern "C" void kernel_launch(void* const* d_in, const int* in_sizes, int n_in,
                              void* d_out, int out_size)
{
    const float* x      = (const float*)d_in[0];   // [1024, 1388]
    const float* conv_w = (const float*)d_in[1];   // [200, 7]
    const float* conv_b = (const float*)d_in[2];   // [200]
    const float* fc_w   = (const float*)d_in[3];   // [91, 188]
    const float* fc_b   = (const float*)d_in[4];   // [91]
    float* out          = (float*)d_out;           // [1024, 91]

    const int B = in_sizes[0] / L_IN;              // 1024 rows
    conv200_kernel<<<B / 2, NT>>>(x, conv_w, conv_b, fc_w, fc_b, out);
}

// round 11
// speedup vs baseline: 1.1163x; 1.1163x over previous
#include <cuda_runtime.h>
#include <cstring>

#define NLAYERS 200
#define KSIZE   7
#define L_IN    1388
#define FC_IN   188
#define FC_OUT  91
#define WPC     7          // 7 rows per CTA, one CTA per SM (147 CTAs for 1024 rows)
#define NT      (32 * WPC)

// Packed dual-fp32 FMA (Blackwell f32x2).
static __device__ __forceinline__ float2 ffma2(float2 a, float2 b, float2 c) {
    unsigned long long ua, ub, uc, ud;
    memcpy(&ua, &a, 8); memcpy(&ub, &b, 8); memcpy(&uc, &c, 8);
    asm("fma.rn.f32x2 %0, %1, %2, %3;" : "=l"(ud) : "l"(ua), "l"(ub), "l"(uc));
    float2 d; memcpy(&d, &ud, 8);
    return d;
}

// Far-pair layout: lane l owns packed positions g = l*C + c, c<C, where
// P[g] = (h[g], h[g+D]) and 32*C == D. Conv taps are ALL pair-aligned:
// P'[g] = sum_k w[k]*P[g+k]. Halo = next lane's first 6 pairs via rotated
// SHFL; lane 31 (seam) takes lane0's .y (wrong .x only feeds the y-half
// tail garbage, which tracks the shrinking valid length). Weights/bias are
// double-buffered one layer ahead so the j=0 FFMA2 never waits on LDS.
template<int C>
static __device__ __forceinline__ void phase(float2* p, int layer0, int nl,
                                             const float2* __restrict__ ws2,
                                             const float2* __restrict__ bs2,
                                             int lane)
{
    static_assert(C >= 6, "seam halo spans one lane only");
    float2 wb[KSIZE + 1];
    #pragma unroll
    for (int k = 0; k < KSIZE; k++) wb[k] = ws2[layer0 * KSIZE + k];
    wb[KSIZE] = bs2[layer0];

    #pragma unroll 1
    for (int i = 0; i < nl; i++) {
        const int L = layer0 + i;
        float2 w[KSIZE];
        #pragma unroll
        for (int k = 0; k < KSIZE; k++) w[k] = wb[k];
        const float2 b = wb[KSIZE];

        const int Lp = (L + 1 < NLAYERS) ? L + 1 : L;   // prefetch next layer
        #pragma unroll
        for (int k = 0; k < KSIZE; k++) wb[k] = ws2[Lp * KSIZE + k];
        wb[KSIZE] = bs2[Lp];

        float2 rot[6];
        #pragma unroll
        for (int m = 0; m < 6; m++) {
            float rx = __shfl_sync(0xffffffffu, p[m].x, lane + 1); // 31 wraps to 0
            float ry = __shfl_sync(0xffffffffu, p[m].y, lane + 1);
            rot[m] = make_float2((lane == 31) ? ry : rx, ry);
        }

        const bool relu = (L != NLAYERS - 1);
        #pragma unroll
        for (int j = 0; j < C; j++) {
            float2 acc = b;
            acc = ffma2(w[0], p[j], acc);
            #pragma unroll
            for (int k = 1; k < KSIZE; k++) {
                float2 v = (j + k < C) ? p[j + k] : rot[j + k - C];
                acc = ffma2(w[k], v, acc);
            }
            if (relu) { acc.x = fmaxf(acc.x, 0.0f); acc.y = fmaxf(acc.y, 0.0f); }
            p[j] = acc;   // ascending in-place: p[j] only read by outputs <= j
        }
    }
}

// Re-split from (DO, CO) to (DN, CN) through the per-warp float stage.
// VF = valid element count at the fold layer.
template<int CO, int CN, int DO, int DN, int VF>
static __device__ __forceinline__ void fold(float2* p, float* stg, int lane)
{
    __syncwarp();
    for (int j = lane; j < 2 * DN; j += 32) stg[j] = 0.0f;
    __syncwarp();
    #pragma unroll
    for (int c = 0; c < CO; c++) {
        int g = lane * CO + c;
        stg[g] = p[c].x;                       // x half: h[0..DO)
        if (DO + g < VF) stg[DO + g] = p[c].y; // y half: h[DO..VF)
    }
    __syncwarp();
    #pragma unroll
    for (int c = 0; c < CN; c++) {
        int g = lane * CN + c;
        p[c] = make_float2(stg[g], stg[g + DN]);
    }
    __syncwarp();
}

__global__ __launch_bounds__(NT, 1)
void conv200_kernel(const float* __restrict__ x,
                    const float* __restrict__ conv_w,
                    const float* __restrict__ conv_b,
                    const float* __restrict__ fc_w,
                    const float* __restrict__ fc_b,
                    float* __restrict__ out,
                    int nrows)
{
    __shared__ __align__(16) float stg_all[WPC][1024];   // 28 KB per-warp stages
    __shared__ float2 ws2[NLAYERS * KSIZE];              // 11.2 KB packed (w,w)
    __shared__ float2 bs2[NLAYERS];                      // 1.6 KB packed (b,b)

    const int t    = threadIdx.x;
    const int wid  = t >> 5;
    const int lane = t & 31;

    for (int j = t; j < NLAYERS * KSIZE; j += NT) {
        float w = conv_w[j];
        ws2[j] = make_float2(w, w);
    }
    for (int j = t; j < NLAYERS; j += NT) {
        float b = conv_b[j];
        bs2[j] = make_float2(b, b);
    }
    __syncthreads();   // only block-wide barrier

    const int row = blockIdx.x * WPC + wid;   // one warp = one row
    if (row >= nrows) return;
    const float* xr = x + (size_t)row * L_IN;
    float* stg = stg_all[wid];

    // ---- initial far-pair pack: D=704, C=22 (two coalesced passes) ----
    float2 p[22];
    for (int j = lane; j < 1024; j += 32) stg[j] = __ldg(&xr[j]);
    __syncwarp();
    #pragma unroll
    for (int c = 0; c < 22; c++) {
        int g = lane * 22 + c;
        p[c].x = stg[g];
        p[c].y = (704 + g < 1024) ? stg[704 + g] : 0.0f;
    }
    __syncwarp();
    for (int j = lane; j < 384; j += 32) {
        int s = 1024 + j;
        stg[j] = (s < L_IN) ? __ldg(&xr[s]) : 0.0f;
    }
    __syncwarp();
    #pragma unroll
    for (int c = 0; c < 22; c++) {
        int g = lane * 22 + c;
        if (704 + g >= 1024) p[c].y = stg[704 + g - 1024];
    }

    // ---- 200 layers: 5 phases, 4 folds. V(i) = 1388 - 6i ----
    phase<22>(p,   0, 61, ws2, bs2, lane);            // D=704
    fold<22, 16, 704, 512, 1022>(p, stg, lane);
    phase<16>(p,  61, 43, ws2, bs2, lane);            // D=512
    fold<16, 12, 512, 384,  764>(p, stg, lane);
    phase<12>(p, 104, 42, ws2, bs2, lane);            // D=384
    fold<12,  8, 384, 256,  512>(p, stg, lane);
    phase< 8>(p, 146, 22, ws2, bs2, lane);            // D=256
    fold< 8,  6, 256, 192,  380>(p, stg, lane);
    phase< 6>(p, 168, 32, ws2, bs2, lane);            // D=192, final V=188<=192

    // ---- gather final 188 elements (all in x half) ----
    __syncwarp();
    #pragma unroll
    for (int c = 0; c < 6; c++) stg[lane * 6 + c] = p[c].x;   // fills [0,192)
    __syncwarp();

    // ---- FC 188->91 + sigmoid: lane handles outputs {lane, lane+32, lane+64} ----
    {
        const float2* hv2 = reinterpret_cast<const float2*>(stg);
        const float2* fw2 = reinterpret_cast<const float2*>(fc_w);
        float2 acc[3];
        #pragma unroll
        for (int u = 0; u < 3; u++) acc[u] = make_float2(0.0f, 0.0f);
        int o0 = lane, o1 = lane + 32, o2 = lane + 64;
        int c2 = (o2 < FC_OUT) ? o2 : (FC_OUT - 1);
        const float2* r0w = fw2 + (size_t)o0 * (FC_IN / 2);
        const float2* r1w = fw2 + (size_t)o1 * (FC_IN / 2);
        const float2* r2w = fw2 + (size_t)c2 * (FC_IN / 2);
        #pragma unroll 2
        for (int j = 0; j < FC_IN / 2; j++) {
            float2 hv = hv2[j];
            acc[0] = ffma2(__ldg(&r0w[j]), hv, acc[0]);
            acc[1] = ffma2(__ldg(&r1w[j]), hv, acc[1]);
            acc[2] = ffma2(__ldg(&r2w[j]), hv, acc[2]);
        }
        float* orow = out + (size_t)row * FC_OUT;
        float s0 = acc[0].x + acc[0].y + __ldg(&fc_b[o0]);
        float s1 = acc[1].x + acc[1].y + __ldg(&fc_b[o1]);
        orow[o0] = 1.0f / (1.0f + __expf(-s0));
        orow[o1] = 1.0f / (1.0f + __expf(-s1));
        if (o2 < FC_OUT) {
            float s2 = acc[2].x + acc[2].y + __ldg(&fc_b[o2]);
            orow[o2] = 1.0f / (1.0f + __expf(-s2));
        }
    }
}

extern "C" void kernel_launch(void* const* d_in, const int* in_sizes, int n_in,
                              void* d_out, int out_size)
{
    const float* x      = (const float*)d_in[0];   // [1024, 1388]
    const float* conv_w = (const float*)d_in[1];   // [200, 7]
    const float* conv_b = (const float*)d_in[2];   // [200]
    const float* fc_w   = (const float*)d_in[3];   // [91, 188]
    const float* fc_b   = (const float*)d_in[4];   // [91]
    float* out          = (float*)d_out;           // [1024, 91]

    const int B = in_sizes[0] / L_IN;              // 1024 rows
    const int grid = (B + WPC - 1) / WPC;          // 147 CTAs (~one per SM)
    conv200_kernel<<<grid, NT>>>(x, conv_w, conv_b, fc_w, fc_b, out, B);
}

// round 12
// speedup vs baseline: 1.2113x; 1.0851x over previous
#include <cuda_runtime.h>
#include <cstring>

#define NLAYERS 200
#define KSIZE   7
#define L_IN    1388
#define FC_IN   188
#define FC_OUT  91
#define WPC     7          // 7 rows per CTA, one CTA per SM (147 CTAs for 1024 rows)
#define NT      (32 * WPC)

// Conv weights/biases pre-packed as (w,w)/(b,b) in constant memory.
// Warp-uniform index -> LDCU -> uniform registers -> FFMA2 with UR operand
// reads only 2 even + 2 odd RF banks (rt 3 -> 2).
__constant__ float2 cws[NLAYERS * KSIZE];
__constant__ float2 cbs[NLAYERS];

// Packed dual-fp32 FMA (Blackwell f32x2).
static __device__ __forceinline__ float2 ffma2(float2 a, float2 b, float2 c) {
    unsigned long long ua, ub, uc, ud;
    memcpy(&ua, &a, 8); memcpy(&ub, &b, 8); memcpy(&uc, &c, 8);
    asm("fma.rn.f32x2 %0, %1, %2, %3;" : "=l"(ud) : "l"(ua), "l"(ub), "l"(uc));
    float2 d; memcpy(&d, &ud, 8);
    return d;
}

// Far-pair layout: lane l owns packed positions g = l*C + c, c<C, where
// P[g] = (h[g], h[g+D]) and 32*C == D. Conv taps are ALL pair-aligned:
// P'[g] = sum_k w[k]*P[g+k]. Halo = next lane's first 6 pairs via rotated
// SHFL; lane 31 (seam) takes lane0's .y (wrong .x only feeds the y-half
// tail garbage, which tracks the shrinking valid length). Weights/bias are
// double-buffered one layer ahead so j=0 never waits on the constant load.
template<int C>
static __device__ __forceinline__ void phase(float2* p, int layer0, int nl,
                                             int lane)
{
    static_assert(C >= 6, "seam halo spans one lane only");
    float2 wb[KSIZE + 1];
    #pragma unroll
    for (int k = 0; k < KSIZE; k++) wb[k] = cws[layer0 * KSIZE + k];
    wb[KSIZE] = cbs[layer0];

    #pragma unroll 1
    for (int i = 0; i < nl; i++) {
        const int L = layer0 + i;
        float2 w[KSIZE];
        #pragma unroll
        for (int k = 0; k < KSIZE; k++) w[k] = wb[k];
        const float2 b = wb[KSIZE];

        const int Lp = (L + 1 < NLAYERS) ? L + 1 : L;   // prefetch next layer
        #pragma unroll
        for (int k = 0; k < KSIZE; k++) wb[k] = cws[Lp * KSIZE + k];
        wb[KSIZE] = cbs[Lp];

        float2 rot[6];
        #pragma unroll
        for (int m = 0; m < 6; m++) {
            float rx = __shfl_sync(0xffffffffu, p[m].x, lane + 1); // 31 wraps to 0
            float ry = __shfl_sync(0xffffffffu, p[m].y, lane + 1);
            rot[m] = make_float2((lane == 31) ? ry : rx, ry);
        }

        const bool relu = (L != NLAYERS - 1);
        #pragma unroll
        for (int j = 0; j < C; j++) {
            float2 acc = b;
            acc = ffma2(w[0], p[j], acc);
            #pragma unroll
            for (int k = 1; k < KSIZE; k++) {
                float2 v = (j + k < C) ? p[j + k] : rot[j + k - C];
                acc = ffma2(w[k], v, acc);
            }
            if (relu) { acc.x = fmaxf(acc.x, 0.0f); acc.y = fmaxf(acc.y, 0.0f); }
            p[j] = acc;   // ascending in-place: p[j] only read by outputs <= j
        }
    }
}

// Re-split from (DO, CO) to (DN, CN) through the per-warp float stage.
// VF = valid element count at the fold layer.
template<int CO, int CN, int DO, int DN, int VF>
static __device__ __forceinline__ void fold(float2* p, float* stg, int lane)
{
    __syncwarp();
    for (int j = lane; j < 2 * DN; j += 32) stg[j] = 0.0f;
    __syncwarp();
    #pragma unroll
    for (int c = 0; c < CO; c++) {
        int g = lane * CO + c;
        stg[g] = p[c].x;                       // x half: h[0..DO)
        if (DO + g < VF) stg[DO + g] = p[c].y; // y half: h[DO..VF)
    }
    __syncwarp();
    #pragma unroll
    for (int c = 0; c < CN; c++) {
        int g = lane * CN + c;
        p[c] = make_float2(stg[g], stg[g + DN]);
    }
    __syncwarp();
}

__global__ __launch_bounds__(NT, 1)
void conv200_kernel(const float* __restrict__ x,
                    const float* __restrict__ fc_w,
                    const float* __restrict__ fc_b,
                    float* __restrict__ out,
                    int nrows)
{
    __shared__ __align__(16) float stg_all[WPC][1024];   // 28 KB per-warp stages

    const int t    = threadIdx.x;
    const int wid  = t >> 5;
    const int lane = t & 31;

    const int row = blockIdx.x * WPC + wid;   // one warp = one row
    if (row >= nrows) return;
    const float* xr = x + (size_t)row * L_IN;
    float* stg = stg_all[wid];

    // ---- initial far-pair pack: D=704, C=22 (two coalesced passes) ----
    float2 p[22];
    for (int j = lane; j < 1024; j += 32) stg[j] = __ldg(&xr[j]);
    __syncwarp();
    #pragma unroll
    for (int c = 0; c < 22; c++) {
        int g = lane * 22 + c;
        p[c].x = stg[g];
        p[c].y = (704 + g < 1024) ? stg[704 + g] : 0.0f;
    }
    __syncwarp();
    for (int j = lane; j < 384; j += 32) {
        int s = 1024 + j;
        stg[j] = (s < L_IN) ? __ldg(&xr[s]) : 0.0f;
    }
    __syncwarp();
    #pragma unroll
    for (int c = 0; c < 22; c++) {
        int g = lane * 22 + c;
        if (704 + g >= 1024) p[c].y = stg[704 + g - 1024];
    }

    // ---- 200 layers: 5 phases, 4 folds. V(i) = 1388 - 6i ----
    phase<22>(p,   0, 61, lane);            // D=704
    fold<22, 16, 704, 512, 1022>(p, stg, lane);
    phase<16>(p,  61, 43, lane);            // D=512
    fold<16, 12, 512, 384,  764>(p, stg, lane);
    phase<12>(p, 104, 42, lane);            // D=384
    fold<12,  8, 384, 256,  512>(p, stg, lane);
    phase< 8>(p, 146, 22, lane);            // D=256
    fold< 8,  6, 256, 192,  380>(p, stg, lane);
    phase< 6>(p, 168, 32, lane);            // D=192, final V=188<=192

    // ---- gather final 188 elements (all in x half) ----
    __syncwarp();
    #pragma unroll
    for (int c = 0; c < 6; c++) stg[lane * 6 + c] = p[c].x;   // fills [0,192)
    __syncwarp();

    // ---- FC 188->91 + sigmoid: lane handles outputs {lane, lane+32, lane+64} ----
    {
        const float2* hv2 = reinterpret_cast<const float2*>(stg);
        const float2* fw2 = reinterpret_cast<const float2*>(fc_w);
        float2 acc[3];
        #pragma unroll
        for (int u = 0; u < 3; u++) acc[u] = make_float2(0.0f, 0.0f);
        int o0 = lane, o1 = lane + 32, o2 = lane + 64;
        int c2 = (o2 < FC_OUT) ? o2 : (FC_OUT - 1);
        const float2* r0w = fw2 + (size_t)o0 * (FC_IN / 2);
        const float2* r1w = fw2 + (size_t)o1 * (FC_IN / 2);
        const float2* r2w = fw2 + (size_t)c2 * (FC_IN / 2);
        #pragma unroll 2
        for (int j = 0; j < FC_IN / 2; j++) {
            float2 hv = hv2[j];
            acc[0] = ffma2(__ldg(&r0w[j]), hv, acc[0]);
            acc[1] = ffma2(__ldg(&r1w[j]), hv, acc[1]);
            acc[2] = ffma2(__ldg(&r2w[j]), hv, acc[2]);
        }
        float* orow = out + (size_t)row * FC_OUT;
        float s0 = acc[0].x + acc[0].y + __ldg(&fc_b[o0]);
        float s1 = acc[1].x + acc[1].y + __ldg(&fc_b[o1]);
        orow[o0] = 1.0f / (1.0f + __expf(-s0));
        orow[o1] = 1.0f / (1.0f + __expf(-s1));
        if (o2 < FC_OUT) {
            float s2 = acc[2].x + acc[2].y + __ldg(&fc_b[o2]);
            orow[o2] = 1.0f / (1.0f + __expf(-s2));
        }
    }
}

extern "C" void kernel_launch(void* const* d_in, const int* in_sizes, int n_in,
                              void* d_out, int out_size)
{
    const float* x      = (const float*)d_in[0];   // [1024, 1388]
    const float* conv_w = (const float*)d_in[1];   // [200, 7]
    const float* conv_b = (const float*)d_in[2];   // [200]
    const float* fc_w   = (const float*)d_in[3];   // [91, 188]
    const float* fc_b   = (const float*)d_in[4];   // [91]
    float* out          = (float*)d_out;           // [1024, 91]

    // Pack (w,w)/(b,b) pairs into constant memory with pitched D2D copies
    // (graph-capturable memcpy nodes; no allocations).
    void* ws_ptr = nullptr; void* bs_ptr = nullptr;
    cudaGetSymbolAddress(&ws_ptr, cws);
    cudaGetSymbolAddress(&bs_ptr, cbs);
    cudaMemcpy2DAsync(ws_ptr, 8, conv_w, 4, 4, NLAYERS * KSIZE,
                      cudaMemcpyDeviceToDevice);
    cudaMemcpy2DAsync((char*)ws_ptr + 4, 8, conv_w, 4, 4, NLAYERS * KSIZE,
                      cudaMemcpyDeviceToDevice);
    cudaMemcpy2DAsync(bs_ptr, 8, conv_b, 4, 4, NLAYERS,
                      cudaMemcpyDeviceToDevice);
    cudaMemcpy2DAsync((char*)bs_ptr + 4, 8, conv_b, 4, 4, NLAYERS,
                      cudaMemcpyDeviceToDevice);

    const int B = in_sizes[0] / L_IN;              // 1024 rows
    const int grid = (B + WPC - 1) / WPC;          // 147 CTAs (~one per SM)
    conv200_kernel<<<grid, NT>>>(x, fc_w, fc_b, out, B);
}

// round 13
// speedup vs baseline: 1.2704x; 1.0487x over previous
#include <cuda_runtime.h>
#include <cstring>

#define NLAYERS 200
#define KSIZE   7
#define L_IN    1388
#define FC_IN   188
#define FC_OUT  91
#define WPC     7          // 7 rows per CTA, one CTA per SM (147 CTAs for 1024 rows)
#define NT      (32 * WPC)
#define STG_N   1408       // per-warp float stage (2*32*22)

// Conv weights/biases pre-packed as (w,w)/(b,b) in constant memory.
__constant__ float2 cws[NLAYERS * KSIZE];
__constant__ float2 cbs[NLAYERS];

// Packed dual-fp32 FMA (Blackwell f32x2).
static __device__ __forceinline__ float2 ffma2(float2 a, float2 b, float2 c) {
    unsigned long long ua, ub, uc, ud;
    memcpy(&ua, &a, 8); memcpy(&ub, &b, 8); memcpy(&uc, &c, 8);
    asm("fma.rn.f32x2 %0, %1, %2, %3;" : "=l"(ud) : "l"(ua), "l"(ub), "l"(uc));
    float2 d; memcpy(&d, &ud, 8);
    return d;
}

// Far-pair layout: lane l owns packed positions g = l*C + c, c<C, where
// P[g] = (h[g], h[g+D]) and 32*C == D. Conv taps are ALL pair-aligned:
// P'[g] = sum_k w[k]*P[g+k]. Halo = next lane's first 6 pairs via rotated
// SHFL; lane 31 (seam) takes lane0's .y (the wrong .x only feeds y-half
// tail garbage, which stays right of the shrinking valid length).
template<int C>
static __device__ __forceinline__ void phase(float2* p, int layer0, int nl,
                                             int lane)
{
    static_assert(C >= 6, "seam halo spans one lane only");
    float2 wb[KSIZE + 1];
    #pragma unroll
    for (int k = 0; k < KSIZE; k++) wb[k] = cws[layer0 * KSIZE + k];
    wb[KSIZE] = cbs[layer0];

    #pragma unroll 1
    for (int i = 0; i < nl; i++) {
        const int L = layer0 + i;
        float2 w[KSIZE];
        #pragma unroll
        for (int k = 0; k < KSIZE; k++) w[k] = wb[k];
        const float2 b = wb[KSIZE];

        const int Lp = (L + 1 < NLAYERS) ? L + 1 : L;   // prefetch next layer
        #pragma unroll
        for (int k = 0; k < KSIZE; k++) wb[k] = cws[Lp * KSIZE + k];
        wb[KSIZE] = cbs[Lp];

        float2 rot[6];
        #pragma unroll
        for (int m = 0; m < 6; m++) {
            float rx = __shfl_sync(0xffffffffu, p[m].x, lane + 1); // 31 wraps to 0
            float ry = __shfl_sync(0xffffffffu, p[m].y, lane + 1);
            rot[m] = make_float2((lane == 31) ? ry : rx, ry);
        }

        const bool relu = (L != NLAYERS - 1);
        #pragma unroll
        for (int j = 0; j < C; j++) {
            float2 acc = b;
            acc = ffma2(w[0], p[j], acc);
            #pragma unroll
            for (int k = 1; k < KSIZE; k++) {
                float2 v = (j + k < C) ? p[j + k] : rot[j + k - C];
                acc = ffma2(w[k], v, acc);
            }
            if (relu) { acc.x = fmaxf(acc.x, 0.0f); acc.y = fmaxf(acc.y, 0.0f); }
            p[j] = acc;   // ascending in-place: p[j] only read by outputs <= j
        }
    }
}

// Re-split from (DO=32*CO, CO) to (DN=32*CN, CN) through the per-warp stage.
// VF = valid element count at the fold layer. x half h[0..DO) is fully valid
// (DO < VF always); y half valid on [DO, VF); zero-fill only [VF, 2*DN).
template<int CO, int CN, int VF>
static __device__ __forceinline__ void fold(float2* p, float* stg, int lane)
{
    const int DO = 32 * CO, DN = 32 * CN;
    __syncwarp();
    #pragma unroll
    for (int c = 0; c < CO; c++) {
        int g = lane * CO + c;
        stg[g] = p[c].x;                       // x half: h[0..DO)
        if (DO + g < VF) stg[DO + g] = p[c].y; // y half: h[DO..VF)
    }
    for (int j = VF + lane; j < 2 * DN; j += 32) stg[j] = 0.0f;
    __syncwarp();
    #pragma unroll
    for (int c = 0; c < CN; c++) {
        int g = lane * CN + c;
        p[c] = make_float2(stg[g], stg[g + DN]);
    }
    __syncwarp();
}

__global__ __launch_bounds__(NT, 1)
void conv200_kernel(const float* __restrict__ x,
                    const float* __restrict__ fc_w,
                    const float* __restrict__ fc_b,
                    float* __restrict__ out,
                    int nrows)
{
    __shared__ __align__(16) float stg_all[WPC][STG_N];   // 38.5 KB per-warp stages

    const int t    = threadIdx.x;
    const int wid  = t >> 5;
    const int lane = t & 31;

    const int row = blockIdx.x * WPC + wid;   // one warp = one row
    if (row >= nrows) return;
    const float* xr = x + (size_t)row * L_IN;
    float* stg = stg_all[wid];

    // ---- initial far-pair pack: D=704, C=22 (single pass, big stage) ----
    for (int j = lane; j < STG_N; j += 32)
        stg[j] = (j < L_IN) ? __ldg(&xr[j]) : 0.0f;
    __syncwarp();
    float2 p[22];
    #pragma unroll
    for (int c = 0; c < 22; c++) {
        int g = lane * 22 + c;
        p[c] = make_float2(stg[g], stg[704 + g]);
    }

    // ---- 200 layers: fold at every integer C (width tracks V = 1388-6i) ----
    phase<22>(p,   0,  8, lane); fold<22, 21, 1340>(p, stg, lane);
    phase<21>(p,   8, 10, lane); fold<21, 20, 1280>(p, stg, lane);
    phase<20>(p,  18, 11, lane); fold<20, 19, 1214>(p, stg, lane);
    phase<19>(p,  29, 11, lane); fold<19, 18, 1148>(p, stg, lane);
    phase<18>(p,  40, 10, lane); fold<18, 17, 1088>(p, stg, lane);
    phase<17>(p,  50, 11, lane); fold<17, 16, 1022>(p, stg, lane);
    phase<16>(p,  61, 11, lane); fold<16, 15,  956>(p, stg, lane);
    phase<15>(p,  72, 10, lane); fold<15, 14,  896>(p, stg, lane);
    phase<14>(p,  82, 11, lane); fold<14, 13,  830>(p, stg, lane);
    phase<13>(p,  93, 11, lane); fold<13, 12,  764>(p, stg, lane);
    phase<12>(p, 104, 10, lane); fold<12, 11,  704>(p, stg, lane);
    phase<11>(p, 114, 11, lane); fold<11, 10,  638>(p, stg, lane);
    phase<10>(p, 125, 11, lane); fold<10,  9,  572>(p, stg, lane);
    phase< 9>(p, 136, 10, lane); fold< 9,  8,  512>(p, stg, lane);
    phase< 8>(p, 146, 11, lane); fold< 8,  7,  446>(p, stg, lane);
    phase< 7>(p, 157, 11, lane); fold< 7,  6,  380>(p, stg, lane);
    phase< 6>(p, 168, 32, lane);                       // D=192, final V=188

    // ---- gather final 188 elements (all in x half) ----
    __syncwarp();
    #pragma unroll
    for (int c = 0; c < 6; c++) stg[lane * 6 + c] = p[c].x;   // fills [0,192)
    __syncwarp();

    // ---- FC 188->91 + sigmoid: lane handles outputs {lane, lane+32, lane+64} ----
    {
        const float2* hv2 = reinterpret_cast<const float2*>(stg);
        const float2* fw2 = reinterpret_cast<const float2*>(fc_w);
        float2 acc[3];
        #pragma unroll
        for (int u = 0; u < 3; u++) acc[u] = make_float2(0.0f, 0.0f);
        int o0 = lane, o1 = lane + 32, o2 = lane + 64;
        int c2 = (o2 < FC_OUT) ? o2 : (FC_OUT - 1);
        const float2* r0w = fw2 + (size_t)o0 * (FC_IN / 2);
        const float2* r1w = fw2 + (size_t)o1 * (FC_IN / 2);
        const float2* r2w = fw2 + (size_t)c2 * (FC_IN / 2);
        #pragma unroll 2
        for (int j = 0; j < FC_IN / 2; j++) {
            float2 hv = hv2[j];
            acc[0] = ffma2(__ldg(&r0w[j]), hv, acc[0]);
            acc[1] = ffma2(__ldg(&r1w[j]), hv, acc[1]);
            acc[2] = ffma2(__ldg(&r2w[j]), hv, acc[2]);
        }
        float* orow = out + (size_t)row * FC_OUT;
        float s0 = acc[0].x + acc[0].y + __ldg(&fc_b[o0]);
        float s1 = acc[1].x + acc[1].y + __ldg(&fc_b[o1]);
        orow[o0] = 1.0f / (1.0f + __expf(-s0));
        orow[o1] = 1.0f / (1.0f + __expf(-s1));
        if (o2 < FC_OUT) {
            float s2 = acc[2].x + acc[2].y + __ldg(&fc_b[o2]);
            orow[o2] = 1.0f / (1.0f + __expf(-s2));
        }
    }
}

extern "C" void kernel_launch(void* const* d_in, const int* in_sizes, int n_in,
                              void* d_out, int out_size)
{
    const float* x      = (const float*)d_in[0];   // [1024, 1388]
    const float* conv_w = (const float*)d_in[1];   // [200, 7]
    const float* conv_b = (const float*)d_in[2];   // [200]
    const float* fc_w   = (const float*)d_in[3];   // [91, 188]
    const float* fc_b   = (const float*)d_in[4];   // [91]
    float* out          = (float*)d_out;           // [1024, 91]

    // Pack (w,w)/(b,b) pairs into constant memory with pitched D2D copies
    // (graph-capturable memcpy nodes; no allocations).
    void* ws_ptr = nullptr; void* bs_ptr = nullptr;
    cudaGetSymbolAddress(&ws_ptr, cws);
    cudaGetSymbolAddress(&bs_ptr, cbs);
    cudaMemcpy2DAsync(ws_ptr, 8, conv_w, 4, 4, NLAYERS * KSIZE,
                      cudaMemcpyDeviceToDevice);
    cudaMemcpy2DAsync((char*)ws_ptr + 4, 8, conv_w, 4, 4, NLAYERS * KSIZE,
                      cudaMemcpyDeviceToDevice);
    cudaMemcpy2DAsync(bs_ptr, 8, conv_b, 4, 4, NLAYERS,
                      cudaMemcpyDeviceToDevice);
    cudaMemcpy2DAsync((char*)bs_ptr + 4, 8, conv_b, 4, 4, NLAYERS,
                      cudaMemcpyDeviceToDevice);

    const int B = in_sizes[0] / L_IN;              // 1024 rows
    const int grid = (B + WPC - 1) / WPC;          // 147 CTAs (~one per SM)
    conv200_kernel<<<grid, NT>>>(x, fc_w, fc_b, out, B);
}